// round 15
// baseline (speedup 1.0000x reference)
#include <cuda_runtime.h>
#include <cuda_bf16.h>
#include <cuda_fp16.h>
#include <math.h>
#include <cstdint>

#define SEQ   2048
#define NH    16
#define NKV   2
#define HD    128
#define QSZ   (NH * HD)            // 2048
#define KVSZ  (NKV * HD)           // 256
#define QKVN  (QSZ + 2 * KVSZ)     // 2560
#define HID   2048
#define GROUPS (NH / NKV)          // 8

// ---------------- scratch (device globals; no allocs allowed) ----------------
__device__ float g_qkv[SEQ * QKVN];
__device__ int   g_pos[SEQ];
__device__ int   g_segstart[SEQ];
__device__ float g_invf[HD / 2];

// fp16 attention operands (2-term path: Q plain, K/V split hi/lo)
__device__ __half g_qf[NH * SEQ * HD];      // [h][s][d]
__device__ __half g_kh[NKV * SEQ * HD];     // [kvh][s][d]
__device__ __half g_kl[NKV * SEQ * HD];
__device__ __half g_vTh[NKV * HD * SEQ];    // [kvh][d][s]  (transposed)
__device__ __half g_vTl[NKV * HD * SEQ];

// fp16 GEMM operands (2-term path: A plain fp16, W split hi/lo fp16)
__device__ __half g_xf16[SEQ * HID];        // activation (hidden, then attn out)
__device__ __half g_wqkvT_h[QKVN * HID];    // w_qkv^T  [2560][2048]
__device__ __half g_wqkvT_l[QKVN * HID];
__device__ __half g_woT_h[HID * QSZ];       // w_o^T    [2048][2048]
__device__ __half g_woT_l[HID * QSZ];

__device__ __forceinline__ uint32_t smem_u32(const void* p) {
    uint32_t a;
    asm("{ .reg .u64 t; cvta.to.shared.u64 t, %1; cvt.u32.u64 %0, t; }" : "=r"(a) : "l"(p));
    return a;
}

#define CP_ASYNC16(smem_addr, gptr) \
    asm volatile("cp.async.cg.shared.global [%0], [%1], 16;\n" \
        :: "r"((uint32_t)(smem_addr)), "l"(gptr))

__device__ __forceinline__ void ldmatrix_x4(uint32_t* r, uint32_t addr) {
    asm volatile("ldmatrix.sync.aligned.m8n8.x4.shared.b16 {%0,%1,%2,%3}, [%4];"
        : "=r"(r[0]), "=r"(r[1]), "=r"(r[2]), "=r"(r[3]) : "r"(addr));
}

__device__ __forceinline__ void mma_fp16(float* c, const uint32_t* a, uint32_t b0, uint32_t b1) {
    asm volatile(
        "mma.sync.aligned.m16n8k16.row.col.f32.f16.f16.f32 "
        "{%0,%1,%2,%3}, {%4,%5,%6,%7}, {%8,%9}, {%0,%1,%2,%3};"
        : "+f"(c[0]), "+f"(c[1]), "+f"(c[2]), "+f"(c[3])
        : "r"(a[0]), "r"(a[1]), "r"(a[2]), "r"(a[3]), "r"(b0), "r"(b1));
}

// pack two fp32 into f16x2 (lo in low half)
__device__ __forceinline__ uint32_t pack_f16(float lo, float hi) {
    uint32_t r;
    asm("cvt.rn.f16x2.f32 %0, %1, %2;" : "=r"(r) : "f"(hi), "f"(lo));
    return r;
}

// ---------------- prep: decode positions (int32/int64), seg scan ----------------
__global__ void prep_kernel(const int* __restrict__ words) {
    __shared__ int chunk_last[256];
    int tid = threadIdx.x;
    int is64 = (words[1] == 0) ? 1 : 0;

    if (tid < HD / 2) {
        g_invf[tid] = (float)(1.0 / pow(1.0e6, (double)(2 * tid) / (double)HD));
    }

    int base = tid * 8;
    int local_pos[8];
    int run = -1;
    #pragma unroll
    for (int e = 0; e < 8; e++) {
        int i = base + e;
        int p = is64 ? words[2 * i] : words[i];
        if (p < 0) p = 0;
        local_pos[e] = p;
        g_pos[i] = p;
        if (p == 0) run = i;
    }
    chunk_last[tid] = run;
    __syncthreads();
    if (tid == 0) {
        int m = -1;
        for (int t = 0; t < 256; t++) {
            int c = chunk_last[t];
            chunk_last[t] = m;
            m = max(m, c);
        }
    }
    __syncthreads();
    int m = chunk_last[tid];
    #pragma unroll
    for (int e = 0; e < 8; e++) {
        int i = base + e;
        if (local_pos[e] == 0) m = i;
        g_segstart[i] = max(m, 0);
    }
}

// ---------------- fp32 -> fp16 (row-major, vectorized) ----------------
__global__ void to_fp16(const float4* __restrict__ X, __half2* __restrict__ H, int n4) {
    int i = blockIdx.x * blockDim.x + threadIdx.x;
    if (i >= n4) return;
    float4 v = X[i];
    H[2 * i]     = __floats2half2_rn(v.x, v.y);
    H[2 * i + 1] = __floats2half2_rn(v.z, v.w);
}

// ---------------- fp32 W[K][N] -> fp16 hi/lo W^T [N][K] ----------------
__global__ void split_transpose_fp16(const float* __restrict__ W,
                                     __half* __restrict__ Th,
                                     __half* __restrict__ Tl, int K, int N) {
    __shared__ float t[32][33];
    int n0 = blockIdx.x * 32, k0 = blockIdx.y * 32;
    int tx = threadIdx.x, ty = threadIdx.y;   // (32, 8)
    #pragma unroll
    for (int i = 0; i < 32; i += 8)
        t[ty + i][tx] = W[(size_t)(k0 + ty + i) * N + n0 + tx];
    __syncthreads();
    #pragma unroll
    for (int i = 0; i < 32; i += 8) {
        float v = t[tx][ty + i];
        __half h = __float2half_rn(v);
        float lo = v - __half2float(h);
        size_t o = (size_t)(n0 + ty + i) * K + k0 + tx;
        Th[o] = h;
        Tl[o] = __float2half_rn(lo);
    }
}

// ====== HMMA GEMM v5: C[M,N](f32) = A * B^T, fp16 2-term (A, Bh+Bl) =========
#define G_STRIDE 40
#define G_A      0u
#define G_BH     10240u
#define G_BL     20480u
#define G_STAGE  30720u

__global__ __launch_bounds__(256, 2)
void gemm_mma5(const __half* __restrict__ A,
               const __half* __restrict__ Bh, const __half* __restrict__ Bl,
               const float* __restrict__ bias, float* __restrict__ C,
               int M, int N, int K)
{
    extern __shared__ char dsm[];
    uint32_t sb = smem_u32(dsm);

    int tid = threadIdx.x, wid = tid >> 5, lane = tid & 31;
    int bx = blockIdx.x, by = blockIdx.y;
    int wm = (wid >> 1) * 32;
    int wn = (wid & 1) * 64;

    size_t arow0 = (size_t)by * 128;
    size_t brow0 = (size_t)bx * 128;

    int a_row = lane & 15;
    int a_k8  = lane >> 4;
    int b_row = (lane & 7) + ((lane >> 4) << 3);
    int b_k8  = (lane >> 3) & 1;

    float acc[2][8][4];
    #pragma unroll
    for (int i = 0; i < 2; i++)
        #pragma unroll
        for (int j = 0; j < 8; j++)
            #pragma unroll
            for (int e = 0; e < 4; e++) acc[i][j][e] = 0.f;

    int nchunks = K >> 5;

    auto prefetch = [&](int kc, int stg) {
        int koff = kc << 5;
        uint32_t st = sb + (uint32_t)stg * G_STAGE;
        #pragma unroll
        for (int u = 0; u < 2; u++) {
            int c = tid + u * 256;
            int r = c >> 2, q = c & 3;
            uint32_t so = (uint32_t)(r * 80 + q * 16);
            CP_ASYNC16(st + G_A  + so, A  + (arow0 + r) * (size_t)K + koff + q * 8);
            CP_ASYNC16(st + G_BH + so, Bh + (brow0 + r) * (size_t)K + koff + q * 8);
            CP_ASYNC16(st + G_BL + so, Bl + (brow0 + r) * (size_t)K + koff + q * 8);
        }
    };

    prefetch(0, 0);
    asm volatile("cp.async.commit_group;\n" ::: "memory");

    for (int kc = 0; kc < nchunks; kc++) {
        int stg = kc & 1;
        if (kc + 1 < nchunks) {
            prefetch(kc + 1, stg ^ 1);
            asm volatile("cp.async.commit_group;\n" ::: "memory");
            asm volatile("cp.async.wait_group 1;\n" ::: "memory");
        } else {
            asm volatile("cp.async.wait_group 0;\n" ::: "memory");
        }
        __syncthreads();
        uint32_t stb = sb + (uint32_t)stg * G_STAGE;

        #pragma unroll
        for (int ds = 0; ds < 2; ds++) {
            uint32_t af[2][4];
            #pragma unroll
            for (int mi = 0; mi < 2; mi++) {
                uint32_t off = (uint32_t)((wm + mi * 16 + a_row) * G_STRIDE + ds * 16 + a_k8 * 8) * 2;
                ldmatrix_x4(af[mi], stb + G_A + off);
            }
            #pragma unroll
            for (int nb = 0; nb < 4; nb++) {
                uint32_t boff = (uint32_t)((wn + nb * 16 + b_row) * G_STRIDE + ds * 16 + b_k8 * 8) * 2;
                uint32_t bhf[4], blf[4];
                ldmatrix_x4(bhf, stb + G_BH + boff);
                ldmatrix_x4(blf, stb + G_BL + boff);
                #pragma unroll
                for (int mi = 0; mi < 2; mi++) {
                    mma_fp16(acc[mi][2 * nb],     af[mi], bhf[0], bhf[1]);
                    mma_fp16(acc[mi][2 * nb],     af[mi], blf[0], blf[1]);
                    mma_fp16(acc[mi][2 * nb + 1], af[mi], bhf[2], bhf[3]);
                    mma_fp16(acc[mi][2 * nb + 1], af[mi], blf[2], blf[3]);
                }
            }
        }
        __syncthreads();
    }

    int trow = lane >> 2;
    int tcol = (lane & 3) * 2;
    #pragma unroll
    for (int mi = 0; mi < 2; mi++) {
        #pragma unroll
        for (int hh = 0; hh < 2; hh++) {
            size_t row = arow0 + wm + mi * 16 + trow + hh * 8;
            float* crow = C + row * (size_t)N + brow0 + wn;
            #pragma unroll
            for (int nj = 0; nj < 8; nj++) {
                int col = nj * 8 + tcol;
                float2 o;
                o.x = acc[mi][nj][2 * hh];
                o.y = acc[mi][nj][2 * hh + 1];
                if (bias) {
                    o.x += bias[brow0 + wn + col];
                    o.y += bias[brow0 + wn + col + 1];
                }
                *(float2*)(crow + col) = o;
            }
        }
    }
}

// ---------------- RoPE + split into fp16 head-major q (plain), k/v (hi/lo) ----------------
__global__ void rope_split_kernel() {
    const int NQ = SEQ * NH * (HD / 2);
    const int NK = SEQ * NKV * (HD / 2);
    const int NV = SEQ * NKV * (HD / 4);
    int idx = blockIdx.x * blockDim.x + threadIdx.x;
    if (idx < NQ) {
        int s   = idx / (NH * (HD / 2));
        int rem = idx % (NH * (HD / 2));
        int h = rem >> 6, j = rem & 63;
        float freq = (float)g_pos[s] * g_invf[j];
        float sn, cs;
        sincosf(freq, &sn, &cs);
        const float* row = g_qkv + (size_t)s * QKVN + h * HD + 2 * j;
        float x1 = row[0], x2 = row[1];
        const float qscale = 0.08838834764831845f;
        float re = (x1 * cs - x2 * sn) * qscale;
        float im = (x1 * sn + x2 * cs) * qscale;
        size_t off = ((size_t)h * SEQ + s) * HD + 2 * j;
        *(__half2*)(g_qf + off) = __floats2half2_rn(re, im);
        return;
    }
    idx -= NQ;
    if (idx < NK) {
        int s   = idx / (NKV * (HD / 2));
        int rem = idx % (NKV * (HD / 2));
        int h = rem >> 6, j = rem & 63;
        float freq = (float)g_pos[s] * g_invf[j];
        float sn, cs;
        sincosf(freq, &sn, &cs);
        const float* row = g_qkv + (size_t)s * QKVN + QSZ + h * HD + 2 * j;
        float x1 = row[0], x2 = row[1];
        float re = x1 * cs - x2 * sn;
        float im = x1 * sn + x2 * cs;
        size_t off = ((size_t)h * SEQ + s) * HD + 2 * j;
        __half hre = __float2half_rn(re), him = __float2half_rn(im);
        __half2 hp; hp.x = hre; hp.y = him;
        *(__half2*)(g_kh + off) = hp;
        __half2 lp;
        lp.x = __float2half_rn(re - __half2float(hre));
        lp.y = __float2half_rn(im - __half2float(him));
        *(__half2*)(g_kl + off) = lp;
        return;
    }
    idx -= NK;
    if (idx < NV) {
        int s = idx / (KVSZ / 4);
        int w = idx % (KVSZ / 4);
        int h = w >> 5;
        int d = (w * 4) & (HD - 1);
        float4 v = *(const float4*)(g_qkv + (size_t)s * QKVN + QSZ + KVSZ + w * 4);
        float vv[4] = {v.x, v.y, v.z, v.w};
        #pragma unroll
        for (int e = 0; e < 4; e++) {
            size_t off = ((size_t)h * HD + d + e) * SEQ + s;
            __half hb = __float2half_rn(vv[e]);
            g_vTh[off] = hb;
            g_vTl[off] = __float2half_rn(vv[e] - __half2float(hb));
        }
    }
}

// ---------------- flash attention v4: fp16 2-term, QT=128, 256 thr, 2 CTAs/SM ----------------
// smem: Q[128][136] @0 (34816) | KH[64][136] @34816 | KL @52224
//       VH[128][72] @69632 (18432) | VL @88064   -> total 106496
#define FB_Q     0u
#define FB_KH    34816u
#define FB_KL    52224u
#define FB_VH    69632u
#define FB_VL    88064u
#define FB_TOTAL 106496

__global__ __launch_bounds__(256, 2) void flash_mma4_kernel() {
    extern __shared__ char sm8[];
    uint32_t sb = smem_u32(sm8);
    __shared__ int s_ktmin;

    int tid = threadIdx.x, wid = tid >> 5, lane = tid & 31;
    int qt = gridDim.x - 1 - blockIdx.x;   // heavy tiles first
    int h = blockIdx.y, kvh = h >> 3;
    int q0 = qt * 128;
    int wm = wid * 16;                     // 8 warps x m16

    int a_row = lane & 15;
    int a_k8  = lane >> 4;
    int b_row = (lane & 7) + ((lane >> 4) << 3);
    int b_k8  = (lane >> 3) & 1;
    uint32_t q_off = (uint32_t)((wm + a_row) * 136 + a_k8 * 8) * 2;

    const char* khg = (const char*)(g_kh + (size_t)kvh * SEQ * HD);
    const char* klg = (const char*)(g_kl + (size_t)kvh * SEQ * HD);
    const char* vhg = (const char*)(g_vTh + (size_t)kvh * HD * SEQ);
    const char* vlg = (const char*)(g_vTl + (size_t)kvh * HD * SEQ);

    auto load_k = [&](int kt) {
        const char* kh = khg + (size_t)kt * 64 * 256;
        const char* kl = klg + (size_t)kt * 64 * 256;
        #pragma unroll
        for (int u = 0; u < 4; u++) {
            int c = tid + u * 256;          // 0..1023 chunks
            int r = c >> 4, cc = c & 15;
            CP_ASYNC16(sb + FB_KH + r * 272 + cc * 16, kh + r * 256 + cc * 16);
            CP_ASYNC16(sb + FB_KL + r * 272 + cc * 16, kl + r * 256 + cc * 16);
        }
    };
    auto load_v = [&](int kt) {
        const char* vh = vhg + (size_t)kt * 128;     // 64 el * 2B
        const char* vl = vlg + (size_t)kt * 128;
        #pragma unroll
        for (int u = 0; u < 4; u++) {
            int c = tid + u * 256;          // 0..1023 chunks
            int vr = c >> 3, vc = c & 7;
            CP_ASYNC16(sb + FB_VH + vr * 144 + vc * 16, vh + (size_t)vr * 4096 + vc * 16);
            CP_ASYNC16(sb + FB_VL + vr * 144 + vc * 16, vl + (size_t)vr * 4096 + vc * 16);
        }
    };

    if (tid == 0) {
        int mn = 0x7fffffff;
        for (int r = 0; r < 128; r++) mn = min(mn, g_segstart[q0 + r]);
        s_ktmin = mn >> 6;
    }
    __syncthreads();
    int ktmin = s_ktmin;
    int ktmax = (q0 + 127) >> 6;

    // prologue: Q + K(ktmin) in group0; V(ktmin) in group1
    {
        const char* qg = (const char*)(g_qf + ((size_t)h * SEQ + q0) * HD);
        #pragma unroll
        for (int u = 0; u < 8; u++) {
            int c = tid + u * 256;          // 0..2047 chunks
            int r = c >> 4, cc = c & 15;
            CP_ASYNC16(sb + FB_Q + r * 272 + cc * 16, qg + r * 256 + cc * 16);
        }
    }
    load_k(ktmin);
    asm volatile("cp.async.commit_group;\n" ::: "memory");
    load_v(ktmin);
    asm volatile("cp.async.commit_group;\n" ::: "memory");

    int sg1 = q0 + wm + (lane >> 2);
    int sg2 = sg1 + 8;
    int ts1 = g_segstart[sg1], ts2 = g_segstart[sg2];

    float o[16][4];
    #pragma unroll
    for (int i = 0; i < 16; i++)
        #pragma unroll
        for (int e = 0; e < 4; e++) o[i][e] = 0.f;
    float m1 = -1e30f, m2 = -1e30f, l1 = 0.f, l2 = 0.f;

    for (int kt = ktmin; kt <= ktmax; kt++) {
        // entering: pending = {K(kt) [+Q first iter], V(kt)} -> drain K, V may stay
        asm volatile("cp.async.wait_group 1;\n" ::: "memory");
        __syncthreads();

        // ---- S = Q K^T : fp16 2-term (Q plain, K hi/lo) ----
        float s[8][4];
        #pragma unroll
        for (int f = 0; f < 8; f++)
            #pragma unroll
            for (int e = 0; e < 4; e++) s[f][e] = 0.f;

        #pragma unroll
        for (int ds = 0; ds < 8; ds++) {
            uint32_t qf[4];
            ldmatrix_x4(qf, sb + FB_Q + q_off + ds * 32);
            #pragma unroll
            for (int nb = 0; nb < 4; nb++) {
                uint32_t koff = (uint32_t)((nb * 16 + b_row) * 136 + ds * 16 + b_k8 * 8) * 2;
                uint32_t khf[4], klf[4];
                ldmatrix_x4(khf, sb + FB_KH + koff);
                ldmatrix_x4(klf, sb + FB_KL + koff);
                mma_fp16(s[2 * nb],     qf, khf[0], khf[1]);
                mma_fp16(s[2 * nb],     qf, klf[0], klf[1]);
                mma_fp16(s[2 * nb + 1], qf, khf[2], khf[3]);
                mma_fp16(s[2 * nb + 1], qf, klf[2], klf[3]);
            }
        }
        __syncthreads();                 // all warps done reading K smem
        if (kt < ktmax) {
            load_k(kt + 1);              // overlaps softmax + PV
            asm volatile("cp.async.commit_group;\n" ::: "memory");
        }

        // ---- mask + online softmax ----
        int colb = kt * 64 + (lane & 3) * 2;
        #pragma unroll
        for (int f = 0; f < 8; f++) {
            int t0 = colb + f * 8, t1 = t0 + 1;
            if (t0 > sg1 || t0 < ts1) s[f][0] = -1e30f;
            if (t1 > sg1 || t1 < ts1) s[f][1] = -1e30f;
            if (t0 > sg2 || t0 < ts2) s[f][2] = -1e30f;
            if (t1 > sg2 || t1 < ts2) s[f][3] = -1e30f;
        }

        float mx1 = -1e30f, mx2 = -1e30f;
        #pragma unroll
        for (int f = 0; f < 8; f++) {
            mx1 = fmaxf(mx1, fmaxf(s[f][0], s[f][1]));
            mx2 = fmaxf(mx2, fmaxf(s[f][2], s[f][3]));
        }
        mx1 = fmaxf(mx1, __shfl_xor_sync(0xffffffffu, mx1, 1));
        mx1 = fmaxf(mx1, __shfl_xor_sync(0xffffffffu, mx1, 2));
        mx2 = fmaxf(mx2, __shfl_xor_sync(0xffffffffu, mx2, 1));
        mx2 = fmaxf(mx2, __shfl_xor_sync(0xffffffffu, mx2, 2));
        float mn1 = fmaxf(m1, mx1), mn2 = fmaxf(m2, mx2);
        float a1 = __expf(m1 - mn1), a2 = __expf(m2 - mn2);
        m1 = mn1; m2 = mn2;

        float sum1 = 0.f, sum2 = 0.f;
        #pragma unroll
        for (int f = 0; f < 8; f++) {
            s[f][0] = __expf(s[f][0] - mn1);
            s[f][1] = __expf(s[f][1] - mn1);
            s[f][2] = __expf(s[f][2] - mn2);
            s[f][3] = __expf(s[f][3] - mn2);
            sum1 += s[f][0] + s[f][1];
            sum2 += s[f][2] + s[f][3];
        }
        sum1 += __shfl_xor_sync(0xffffffffu, sum1, 1);
        sum1 += __shfl_xor_sync(0xffffffffu, sum1, 2);
        sum2 += __shfl_xor_sync(0xffffffffu, sum2, 1);
        sum2 += __shfl_xor_sync(0xffffffffu, sum2, 2);
        l1 = l1 * a1 + sum1;
        l2 = l2 * a2 + sum2;

        #pragma unroll
        for (int i = 0; i < 16; i++) {
            o[i][0] *= a1; o[i][1] *= a1;
            o[i][2] *= a2; o[i][3] *= a2;
        }

        // V(kt) must complete. kt<ktmax: pending={V(kt),K(kt+1)} -> wait 1.
        // Last iteration: pending={V(kt)} alone -> wait 0 (round-12 NaN fix).
        if (kt < ktmax) {
            asm volatile("cp.async.wait_group 1;\n" ::: "memory");
        } else {
            asm volatile("cp.async.wait_group 0;\n" ::: "memory");
        }
        __syncthreads();

        // ---- O += P V : fp16 2-term (P plain, V hi/lo) ----
        #pragma unroll
        for (int kk = 0; kk < 4; kk++) {
            uint32_t ph[4];
            ph[0] = pack_f16(s[2 * kk][0],     s[2 * kk][1]);
            ph[1] = pack_f16(s[2 * kk][2],     s[2 * kk][3]);
            ph[2] = pack_f16(s[2 * kk + 1][0], s[2 * kk + 1][1]);
            ph[3] = pack_f16(s[2 * kk + 1][2], s[2 * kk + 1][3]);
            #pragma unroll
            for (int nb = 0; nb < 8; nb++) {
                uint32_t voff = (uint32_t)((nb * 16 + b_row) * 72 + kk * 16 + b_k8 * 8) * 2;
                uint32_t vhf[4], vlf[4];
                ldmatrix_x4(vhf, sb + FB_VH + voff);
                ldmatrix_x4(vlf, sb + FB_VL + voff);
                mma_fp16(o[2 * nb],     ph, vhf[0], vhf[1]);
                mma_fp16(o[2 * nb],     ph, vlf[0], vlf[1]);
                mma_fp16(o[2 * nb + 1], ph, vhf[2], vhf[3]);
                mma_fp16(o[2 * nb + 1], ph, vlf[2], vlf[3]);
            }
        }
        __syncthreads();                 // all warps done reading V smem
        if (kt < ktmax) {
            load_v(kt + 1);
            asm volatile("cp.async.commit_group;\n" ::: "memory");
        }
    }

    // ---- finalize: write attn output directly as fp16 (O-proj A operand) ----
    float rn1 = (l1 > 0.f) ? 1.f / l1 : 0.f;
    float rn2 = (l2 > 0.f) ? 1.f / l2 : 0.f;
    int row1 = q0 + wm + (lane >> 2);
    int row2 = row1 + 8;
    #pragma unroll
    for (int nf = 0; nf < 16; nf++) {
        int col = h * HD + nf * 8 + (lane & 3) * 2;
        *(__half2*)&g_xf16[(size_t)row1 * QSZ + col] =
            __floats2half2_rn(o[nf][0] * rn1, o[nf][1] * rn1);
        *(__half2*)&g_xf16[(size_t)row2 * QSZ + col] =
            __floats2half2_rn(o[nf][2] * rn2, o[nf][3] * rn2);
    }
}

// ---------------- launch ----------------
extern "C" void kernel_launch(void* const* d_in, const int* in_sizes, int n_in,
                              void* d_out, int out_size) {
    const float* hidden = (const float*)d_in[0];
    const int*   posw   = (const int*)d_in[1];
    const float* w_qkv  = (const float*)d_in[2];
    const float* b_qkv  = (const float*)d_in[3];
    const float* w_o    = (const float*)d_in[4];
    float* out = (float*)d_out;

    void *p_qkv = nullptr, *p_x = nullptr;
    void *p_wqh = nullptr, *p_wql = nullptr, *p_woh = nullptr, *p_wol = nullptr;
    cudaGetSymbolAddress(&p_qkv, g_qkv);
    cudaGetSymbolAddress(&p_x, g_xf16);
    cudaGetSymbolAddress(&p_wqh, g_wqkvT_h);
    cudaGetSymbolAddress(&p_wql, g_wqkvT_l);
    cudaGetSymbolAddress(&p_woh, g_woT_h);
    cudaGetSymbolAddress(&p_wol, g_woT_l);

    const int gemm_smem = 2 * G_STAGE;   // 61440
    cudaFuncSetAttribute(gemm_mma5, cudaFuncAttributeMaxDynamicSharedMemorySize, gemm_smem);

    prep_kernel<<<1, 256>>>(posw);

    to_fp16<<<(SEQ * HID / 4 + 255) / 256, 256>>>(
        (const float4*)hidden, (__half2*)p_x, SEQ * HID / 4);
    split_transpose_fp16<<<dim3(QKVN / 32, HID / 32), dim3(32, 8)>>>(
        w_qkv, (__half*)p_wqh, (__half*)p_wql, HID, QKVN);
    split_transpose_fp16<<<dim3(HID / 32, QSZ / 32), dim3(32, 8)>>>(
        w_o, (__half*)p_woh, (__half*)p_wol, QSZ, HID);

    gemm_mma5<<<dim3(QKVN / 128, SEQ / 128), 256, gemm_smem>>>(
        (const __half*)p_x,
        (const __half*)p_wqh, (const __half*)p_wql,
        b_qkv, (float*)p_qkv, SEQ, QKVN, HID);

    int total = SEQ * NH * (HD / 2) + SEQ * NKV * (HD / 2) + SEQ * NKV * (HD / 4);
    rope_split_kernel<<<(total + 255) / 256, 256>>>();

    cudaFuncSetAttribute(flash_mma4_kernel,
                         cudaFuncAttributeMaxDynamicSharedMemorySize, FB_TOTAL);
    flash_mma4_kernel<<<dim3(SEQ / 128, NH), 256, FB_TOTAL>>>();

    gemm_mma5<<<dim3(HID / 128, SEQ / 128), 256, gemm_smem>>>(
        (const __half*)p_x,
        (const __half*)p_woh, (const __half*)p_wol,
        nullptr, out, SEQ, HID, QSZ);
}

// round 16
// speedup vs baseline: 1.1590x; 1.1590x over previous
#include <cuda_runtime.h>
#include <cuda_bf16.h>
#include <cuda_fp16.h>
#include <math.h>
#include <cstdint>

#define SEQ   2048
#define NH    16
#define NKV   2
#define HD    128
#define QSZ   (NH * HD)            // 2048
#define KVSZ  (NKV * HD)           // 256
#define QKVN  (QSZ + 2 * KVSZ)     // 2560
#define HID   2048
#define GROUPS (NH / NKV)          // 8

// ---------------- scratch (device globals; no allocs allowed) ----------------
__device__ float g_qkv[SEQ * QKVN];
__device__ int   g_pos[SEQ];
__device__ int   g_segstart[SEQ];
__device__ float g_invf[HD / 2];

// fp16 attention operands (2-term path: Q plain, K/V split hi/lo)
__device__ __half g_qf[NH * SEQ * HD];      // [h][s][d]
__device__ __half g_kh[NKV * SEQ * HD];     // [kvh][s][d]
__device__ __half g_kl[NKV * SEQ * HD];
__device__ __half g_vTh[NKV * HD * SEQ];    // [kvh][d][s]  (transposed)
__device__ __half g_vTl[NKV * HD * SEQ];

// fp16 GEMM operands (2-term path: A plain fp16, W split hi/lo fp16)
__device__ __half g_xf16[SEQ * HID];        // activation (hidden, then attn out)
__device__ __half g_wqkvT_h[QKVN * HID];    // w_qkv^T  [2560][2048]
__device__ __half g_wqkvT_l[QKVN * HID];
__device__ __half g_woT_h[HID * QSZ];       // w_o^T    [2048][2048]
__device__ __half g_woT_l[HID * QSZ];

__device__ __forceinline__ uint32_t smem_u32(const void* p) {
    uint32_t a;
    asm("{ .reg .u64 t; cvta.to.shared.u64 t, %1; cvt.u32.u64 %0, t; }" : "=r"(a) : "l"(p));
    return a;
}

#define CP_ASYNC16(smem_addr, gptr) \
    asm volatile("cp.async.cg.shared.global [%0], [%1], 16;\n" \
        :: "r"((uint32_t)(smem_addr)), "l"(gptr))

__device__ __forceinline__ void ldmatrix_x4(uint32_t* r, uint32_t addr) {
    asm volatile("ldmatrix.sync.aligned.m8n8.x4.shared.b16 {%0,%1,%2,%3}, [%4];"
        : "=r"(r[0]), "=r"(r[1]), "=r"(r[2]), "=r"(r[3]) : "r"(addr));
}

__device__ __forceinline__ void mma_fp16(float* c, const uint32_t* a, uint32_t b0, uint32_t b1) {
    asm volatile(
        "mma.sync.aligned.m16n8k16.row.col.f32.f16.f16.f32 "
        "{%0,%1,%2,%3}, {%4,%5,%6,%7}, {%8,%9}, {%0,%1,%2,%3};"
        : "+f"(c[0]), "+f"(c[1]), "+f"(c[2]), "+f"(c[3])
        : "r"(a[0]), "r"(a[1]), "r"(a[2]), "r"(a[3]), "r"(b0), "r"(b1));
}

// pack two fp32 into f16x2 (lo in low half)
__device__ __forceinline__ uint32_t pack_f16(float lo, float hi) {
    uint32_t r;
    asm("cvt.rn.f16x2.f32 %0, %1, %2;" : "=r"(r) : "f"(hi), "f"(lo));
    return r;
}

// ---------------- prep: decode positions (int32/int64), seg scan ----------------
__global__ void prep_kernel(const int* __restrict__ words) {
    __shared__ int chunk_last[256];
    int tid = threadIdx.x;
    int is64 = (words[1] == 0) ? 1 : 0;

    if (tid < HD / 2) {
        g_invf[tid] = (float)(1.0 / pow(1.0e6, (double)(2 * tid) / (double)HD));
    }

    int base = tid * 8;
    int local_pos[8];
    int run = -1;
    #pragma unroll
    for (int e = 0; e < 8; e++) {
        int i = base + e;
        int p = is64 ? words[2 * i] : words[i];
        if (p < 0) p = 0;
        local_pos[e] = p;
        g_pos[i] = p;
        if (p == 0) run = i;
    }
    chunk_last[tid] = run;
    __syncthreads();
    if (tid == 0) {
        int m = -1;
        for (int t = 0; t < 256; t++) {
            int c = chunk_last[t];
            chunk_last[t] = m;
            m = max(m, c);
        }
    }
    __syncthreads();
    int m = chunk_last[tid];
    #pragma unroll
    for (int e = 0; e < 8; e++) {
        int i = base + e;
        if (local_pos[e] == 0) m = i;
        g_segstart[i] = max(m, 0);
    }
}

// ---------------- fp32 -> fp16 (row-major, vectorized) ----------------
__global__ void to_fp16(const float4* __restrict__ X, __half2* __restrict__ H, int n4) {
    int i = blockIdx.x * blockDim.x + threadIdx.x;
    if (i >= n4) return;
    float4 v = X[i];
    H[2 * i]     = __floats2half2_rn(v.x, v.y);
    H[2 * i + 1] = __floats2half2_rn(v.z, v.w);
}

// ---------------- fp32 W[K][N] -> fp16 hi/lo W^T [N][K] ----------------
__global__ void split_transpose_fp16(const float* __restrict__ W,
                                     __half* __restrict__ Th,
                                     __half* __restrict__ Tl, int K, int N) {
    __shared__ float t[32][33];
    int n0 = blockIdx.x * 32, k0 = blockIdx.y * 32;
    int tx = threadIdx.x, ty = threadIdx.y;   // (32, 8)
    #pragma unroll
    for (int i = 0; i < 32; i += 8)
        t[ty + i][tx] = W[(size_t)(k0 + ty + i) * N + n0 + tx];
    __syncthreads();
    #pragma unroll
    for (int i = 0; i < 32; i += 8) {
        float v = t[tx][ty + i];
        __half h = __float2half_rn(v);
        float lo = v - __half2float(h);
        size_t o = (size_t)(n0 + ty + i) * K + k0 + tx;
        Th[o] = h;
        Tl[o] = __float2half_rn(lo);
    }
}

// ====== HMMA GEMM v5: C[M,N](f32) = A * B^T, fp16 2-term (A, Bh+Bl) =========
#define G_STRIDE 40
#define G_A      0u
#define G_BH     10240u
#define G_BL     20480u
#define G_STAGE  30720u

__global__ __launch_bounds__(256, 2)
void gemm_mma5(const __half* __restrict__ A,
               const __half* __restrict__ Bh, const __half* __restrict__ Bl,
               const float* __restrict__ bias, float* __restrict__ C,
               int M, int N, int K)
{
    extern __shared__ char dsm[];
    uint32_t sb = smem_u32(dsm);

    int tid = threadIdx.x, wid = tid >> 5, lane = tid & 31;
    int bx = blockIdx.x, by = blockIdx.y;
    int wm = (wid >> 1) * 32;
    int wn = (wid & 1) * 64;

    size_t arow0 = (size_t)by * 128;
    size_t brow0 = (size_t)bx * 128;

    int a_row = lane & 15;
    int a_k8  = lane >> 4;
    int b_row = (lane & 7) + ((lane >> 4) << 3);
    int b_k8  = (lane >> 3) & 1;

    float acc[2][8][4];
    #pragma unroll
    for (int i = 0; i < 2; i++)
        #pragma unroll
        for (int j = 0; j < 8; j++)
            #pragma unroll
            for (int e = 0; e < 4; e++) acc[i][j][e] = 0.f;

    int nchunks = K >> 5;

    auto prefetch = [&](int kc, int stg) {
        int koff = kc << 5;
        uint32_t st = sb + (uint32_t)stg * G_STAGE;
        #pragma unroll
        for (int u = 0; u < 2; u++) {
            int c = tid + u * 256;
            int r = c >> 2, q = c & 3;
            uint32_t so = (uint32_t)(r * 80 + q * 16);
            CP_ASYNC16(st + G_A  + so, A  + (arow0 + r) * (size_t)K + koff + q * 8);
            CP_ASYNC16(st + G_BH + so, Bh + (brow0 + r) * (size_t)K + koff + q * 8);
            CP_ASYNC16(st + G_BL + so, Bl + (brow0 + r) * (size_t)K + koff + q * 8);
        }
    };

    prefetch(0, 0);
    asm volatile("cp.async.commit_group;\n" ::: "memory");

    for (int kc = 0; kc < nchunks; kc++) {
        int stg = kc & 1;
        if (kc + 1 < nchunks) {
            prefetch(kc + 1, stg ^ 1);
            asm volatile("cp.async.commit_group;\n" ::: "memory");
            asm volatile("cp.async.wait_group 1;\n" ::: "memory");
        } else {
            asm volatile("cp.async.wait_group 0;\n" ::: "memory");
        }
        __syncthreads();
        uint32_t stb = sb + (uint32_t)stg * G_STAGE;

        #pragma unroll
        for (int ds = 0; ds < 2; ds++) {
            uint32_t af[2][4];
            #pragma unroll
            for (int mi = 0; mi < 2; mi++) {
                uint32_t off = (uint32_t)((wm + mi * 16 + a_row) * G_STRIDE + ds * 16 + a_k8 * 8) * 2;
                ldmatrix_x4(af[mi], stb + G_A + off);
            }
            #pragma unroll
            for (int nb = 0; nb < 4; nb++) {
                uint32_t boff = (uint32_t)((wn + nb * 16 + b_row) * G_STRIDE + ds * 16 + b_k8 * 8) * 2;
                uint32_t bhf[4], blf[4];
                ldmatrix_x4(bhf, stb + G_BH + boff);
                ldmatrix_x4(blf, stb + G_BL + boff);
                #pragma unroll
                for (int mi = 0; mi < 2; mi++) {
                    mma_fp16(acc[mi][2 * nb],     af[mi], bhf[0], bhf[1]);
                    mma_fp16(acc[mi][2 * nb],     af[mi], blf[0], blf[1]);
                    mma_fp16(acc[mi][2 * nb + 1], af[mi], bhf[2], bhf[3]);
                    mma_fp16(acc[mi][2 * nb + 1], af[mi], blf[2], blf[3]);
                }
            }
        }
        __syncthreads();
    }

    int trow = lane >> 2;
    int tcol = (lane & 3) * 2;
    #pragma unroll
    for (int mi = 0; mi < 2; mi++) {
        #pragma unroll
        for (int hh = 0; hh < 2; hh++) {
            size_t row = arow0 + wm + mi * 16 + trow + hh * 8;
            float* crow = C + row * (size_t)N + brow0 + wn;
            #pragma unroll
            for (int nj = 0; nj < 8; nj++) {
                int col = nj * 8 + tcol;
                float2 o;
                o.x = acc[mi][nj][2 * hh];
                o.y = acc[mi][nj][2 * hh + 1];
                if (bias) {
                    o.x += bias[brow0 + wn + col];
                    o.y += bias[brow0 + wn + col + 1];
                }
                *(float2*)(crow + col) = o;
            }
        }
    }
}

// ---------------- RoPE + split into fp16 head-major q (plain), k/v (hi/lo) ----------------
__global__ void rope_split_kernel() {
    const int NQ = SEQ * NH * (HD / 2);
    const int NK = SEQ * NKV * (HD / 2);
    const int NV = SEQ * NKV * (HD / 4);
    int idx = blockIdx.x * blockDim.x + threadIdx.x;
    if (idx < NQ) {
        int s   = idx / (NH * (HD / 2));
        int rem = idx % (NH * (HD / 2));
        int h = rem >> 6, j = rem & 63;
        float freq = (float)g_pos[s] * g_invf[j];
        float sn, cs;
        sincosf(freq, &sn, &cs);
        const float* row = g_qkv + (size_t)s * QKVN + h * HD + 2 * j;
        float x1 = row[0], x2 = row[1];
        const float qscale = 0.08838834764831845f;
        float re = (x1 * cs - x2 * sn) * qscale;
        float im = (x1 * sn + x2 * cs) * qscale;
        size_t off = ((size_t)h * SEQ + s) * HD + 2 * j;
        *(__half2*)(g_qf + off) = __floats2half2_rn(re, im);
        return;
    }
    idx -= NQ;
    if (idx < NK) {
        int s   = idx / (NKV * (HD / 2));
        int rem = idx % (NKV * (HD / 2));
        int h = rem >> 6, j = rem & 63;
        float freq = (float)g_pos[s] * g_invf[j];
        float sn, cs;
        sincosf(freq, &sn, &cs);
        const float* row = g_qkv + (size_t)s * QKVN + QSZ + h * HD + 2 * j;
        float x1 = row[0], x2 = row[1];
        float re = x1 * cs - x2 * sn;
        float im = x1 * sn + x2 * cs;
        size_t off = ((size_t)h * SEQ + s) * HD + 2 * j;
        __half hre = __float2half_rn(re), him = __float2half_rn(im);
        __half2 hp; hp.x = hre; hp.y = him;
        *(__half2*)(g_kh + off) = hp;
        __half2 lp;
        lp.x = __float2half_rn(re - __half2float(hre));
        lp.y = __float2half_rn(im - __half2float(him));
        *(__half2*)(g_kl + off) = lp;
        return;
    }
    idx -= NK;
    if (idx < NV) {
        int s = idx / (KVSZ / 4);
        int w = idx % (KVSZ / 4);
        int h = w >> 5;
        int d = (w * 4) & (HD - 1);
        float4 v = *(const float4*)(g_qkv + (size_t)s * QKVN + QSZ + KVSZ + w * 4);
        float vv[4] = {v.x, v.y, v.z, v.w};
        #pragma unroll
        for (int e = 0; e < 4; e++) {
            size_t off = ((size_t)h * HD + d + e) * SEQ + s;
            __half hb = __float2half_rn(vv[e]);
            g_vTh[off] = hb;
            g_vTl[off] = __float2half_rn(vv[e] - __half2float(hb));
        }
    }
}

// ---------------- flash attention v5: fp16 2-term, QT=64, 128 thr, Q in regs, 3 CTAs/SM ----------------
// smem: KH[64][136] @0 (17408) | KL @17408 | VH[128][72] @34816 (18432) | VL @53248
//   -> total 71680.  Q staged through KH region before pipeline start.
#define FB_KH    0u
#define FB_KL    17408u
#define FB_VH    34816u
#define FB_VL    53248u
#define FB_TOTAL 71680

__global__ __launch_bounds__(128, 3) void flash_mma5_kernel() {
    extern __shared__ char sm8[];
    uint32_t sb = smem_u32(sm8);
    __shared__ int s_ktmin;

    int tid = threadIdx.x, wid = tid >> 5, lane = tid & 31;
    int qt = gridDim.x - 1 - blockIdx.x;   // heavy tiles first
    int h = blockIdx.y, kvh = h >> 3;
    int q0 = qt * 64;
    int wm = wid * 16;                     // 4 warps x m16

    int a_row = lane & 15;
    int a_k8  = lane >> 4;
    int b_row = (lane & 7) + ((lane >> 4) << 3);
    int b_k8  = (lane >> 3) & 1;
    uint32_t q_off = (uint32_t)((wm + a_row) * 136 + a_k8 * 8) * 2;

    const char* khg = (const char*)(g_kh + (size_t)kvh * SEQ * HD);
    const char* klg = (const char*)(g_kl + (size_t)kvh * SEQ * HD);
    const char* vhg = (const char*)(g_vTh + (size_t)kvh * HD * SEQ);
    const char* vlg = (const char*)(g_vTl + (size_t)kvh * HD * SEQ);

    auto load_k = [&](int kt) {
        const char* kh = khg + (size_t)kt * 64 * 256;
        const char* kl = klg + (size_t)kt * 64 * 256;
        #pragma unroll
        for (int u = 0; u < 8; u++) {
            int c = tid + u * 128;
            int r = c >> 4, cc = c & 15;
            CP_ASYNC16(sb + FB_KH + r * 272 + cc * 16, kh + r * 256 + cc * 16);
            CP_ASYNC16(sb + FB_KL + r * 272 + cc * 16, kl + r * 256 + cc * 16);
        }
    };
    auto load_v = [&](int kt) {
        const char* vh = vhg + (size_t)kt * 128;     // 64 el * 2B
        const char* vl = vlg + (size_t)kt * 128;
        #pragma unroll
        for (int u = 0; u < 8; u++) {
            int c = tid + u * 128;
            int vr = c >> 3, vc = c & 7;
            CP_ASYNC16(sb + FB_VH + vr * 144 + vc * 16, vh + (size_t)vr * 4096 + vc * 16);
            CP_ASYNC16(sb + FB_VL + vr * 144 + vc * 16, vl + (size_t)vr * 4096 + vc * 16);
        }
    };

    if (tid == 0) {
        int mn = 0x7fffffff;
        for (int r = 0; r < 64; r++) mn = min(mn, g_segstart[q0 + r]);
        s_ktmin = mn >> 6;
    }

    // ---- stage Q through the KH smem region, cache fragments in registers ----
    {
        const char* qg = (const char*)(g_qf + ((size_t)h * SEQ + q0) * HD);
        #pragma unroll
        for (int u = 0; u < 8; u++) {
            int c = tid + u * 128;
            int r = c >> 4, cc = c & 15;
            CP_ASYNC16(sb + FB_KH + r * 272 + cc * 16, qg + r * 256 + cc * 16);
        }
    }
    asm volatile("cp.async.commit_group;\n" ::: "memory");
    asm volatile("cp.async.wait_group 0;\n" ::: "memory");
    __syncthreads();

    uint32_t qreg[8][4];
    #pragma unroll
    for (int ds = 0; ds < 8; ds++)
        ldmatrix_x4(qreg[ds], sb + FB_KH + q_off + ds * 32);
    __syncthreads();                      // all warps done reading staged Q

    int ktmin = s_ktmin;
    int ktmax = qt;

    load_k(ktmin);
    asm volatile("cp.async.commit_group;\n" ::: "memory");
    load_v(ktmin);
    asm volatile("cp.async.commit_group;\n" ::: "memory");

    int sg1 = q0 + wm + (lane >> 2);
    int sg2 = sg1 + 8;
    int ts1 = g_segstart[sg1], ts2 = g_segstart[sg2];

    float o[16][4];
    #pragma unroll
    for (int i = 0; i < 16; i++)
        #pragma unroll
        for (int e = 0; e < 4; e++) o[i][e] = 0.f;
    float m1 = -1e30f, m2 = -1e30f, l1 = 0.f, l2 = 0.f;

    for (int kt = ktmin; kt <= ktmax; kt++) {
        // entering: pending = {K(kt), V(kt)} -> drain K, V may stay
        asm volatile("cp.async.wait_group 1;\n" ::: "memory");
        __syncthreads();

        // ---- S = Q K^T : fp16 2-term (Q regs, K hi/lo) ----
        float s[8][4];
        #pragma unroll
        for (int f = 0; f < 8; f++)
            #pragma unroll
            for (int e = 0; e < 4; e++) s[f][e] = 0.f;

        #pragma unroll
        for (int ds = 0; ds < 8; ds++) {
            #pragma unroll
            for (int nb = 0; nb < 4; nb++) {
                uint32_t koff = (uint32_t)((nb * 16 + b_row) * 136 + ds * 16 + b_k8 * 8) * 2;
                uint32_t khf[4], klf[4];
                ldmatrix_x4(khf, sb + FB_KH + koff);
                ldmatrix_x4(klf, sb + FB_KL + koff);
                mma_fp16(s[2 * nb],     qreg[ds], khf[0], khf[1]);
                mma_fp16(s[2 * nb],     qreg[ds], klf[0], klf[1]);
                mma_fp16(s[2 * nb + 1], qreg[ds], khf[2], khf[3]);
                mma_fp16(s[2 * nb + 1], qreg[ds], klf[2], klf[3]);
            }
        }
        __syncthreads();                 // all warps done reading K smem
        if (kt < ktmax) {
            load_k(kt + 1);              // overlaps softmax + PV
            asm volatile("cp.async.commit_group;\n" ::: "memory");
        }

        // ---- mask + online softmax ----
        int colb = kt * 64 + (lane & 3) * 2;
        #pragma unroll
        for (int f = 0; f < 8; f++) {
            int t0 = colb + f * 8, t1 = t0 + 1;
            if (t0 > sg1 || t0 < ts1) s[f][0] = -1e30f;
            if (t1 > sg1 || t1 < ts1) s[f][1] = -1e30f;
            if (t0 > sg2 || t0 < ts2) s[f][2] = -1e30f;
            if (t1 > sg2 || t1 < ts2) s[f][3] = -1e30f;
        }

        float mx1 = -1e30f, mx2 = -1e30f;
        #pragma unroll
        for (int f = 0; f < 8; f++) {
            mx1 = fmaxf(mx1, fmaxf(s[f][0], s[f][1]));
            mx2 = fmaxf(mx2, fmaxf(s[f][2], s[f][3]));
        }
        mx1 = fmaxf(mx1, __shfl_xor_sync(0xffffffffu, mx1, 1));
        mx1 = fmaxf(mx1, __shfl_xor_sync(0xffffffffu, mx1, 2));
        mx2 = fmaxf(mx2, __shfl_xor_sync(0xffffffffu, mx2, 1));
        mx2 = fmaxf(mx2, __shfl_xor_sync(0xffffffffu, mx2, 2));
        float mn1 = fmaxf(m1, mx1), mn2 = fmaxf(m2, mx2);
        float a1 = __expf(m1 - mn1), a2 = __expf(m2 - mn2);
        m1 = mn1; m2 = mn2;

        float sum1 = 0.f, sum2 = 0.f;
        #pragma unroll
        for (int f = 0; f < 8; f++) {
            s[f][0] = __expf(s[f][0] - mn1);
            s[f][1] = __expf(s[f][1] - mn1);
            s[f][2] = __expf(s[f][2] - mn2);
            s[f][3] = __expf(s[f][3] - mn2);
            sum1 += s[f][0] + s[f][1];
            sum2 += s[f][2] + s[f][3];
        }
        sum1 += __shfl_xor_sync(0xffffffffu, sum1, 1);
        sum1 += __shfl_xor_sync(0xffffffffu, sum1, 2);
        sum2 += __shfl_xor_sync(0xffffffffu, sum2, 1);
        sum2 += __shfl_xor_sync(0xffffffffu, sum2, 2);
        l1 = l1 * a1 + sum1;
        l2 = l2 * a2 + sum2;

        #pragma unroll
        for (int i = 0; i < 16; i++) {
            o[i][0] *= a1; o[i][1] *= a1;
            o[i][2] *= a2; o[i][3] *= a2;
        }

        // V(kt) must complete. kt<ktmax: pending={V(kt),K(kt+1)} -> wait 1.
        // Last iteration: pending={V(kt)} alone -> wait 0 (round-12 NaN fix).
        if (kt < ktmax) {
            asm volatile("cp.async.wait_group 1;\n" ::: "memory");
        } else {
            asm volatile("cp.async.wait_group 0;\n" ::: "memory");
        }
        __syncthreads();

        // ---- O += P V : fp16 2-term (P plain, V hi/lo) ----
        #pragma unroll
        for (int kk = 0; kk < 4; kk++) {
            uint32_t ph[4];
            ph[0] = pack_f16(s[2 * kk][0],     s[2 * kk][1]);
            ph[1] = pack_f16(s[2 * kk][2],     s[2 * kk][3]);
            ph[2] = pack_f16(s[2 * kk + 1][0], s[2 * kk + 1][1]);
            ph[3] = pack_f16(s[2 * kk + 1][2], s[2 * kk + 1][3]);
            #pragma unroll
            for (int nb = 0; nb < 8; nb++) {
                uint32_t voff = (uint32_t)((nb * 16 + b_row) * 72 + kk * 16 + b_k8 * 8) * 2;
                uint32_t vhf[4], vlf[4];
                ldmatrix_x4(vhf, sb + FB_VH + voff);
                ldmatrix_x4(vlf, sb + FB_VL + voff);
                mma_fp16(o[2 * nb],     ph, vhf[0], vhf[1]);
                mma_fp16(o[2 * nb],     ph, vlf[0], vlf[1]);
                mma_fp16(o[2 * nb + 1], ph, vhf[2], vhf[3]);
                mma_fp16(o[2 * nb + 1], ph, vlf[2], vlf[3]);
            }
        }
        __syncthreads();                 // all warps done reading V smem
        if (kt < ktmax) {
            load_v(kt + 1);
            asm volatile("cp.async.commit_group;\n" ::: "memory");
        }
    }

    // ---- finalize: write attn output directly as fp16 (O-proj A operand) ----
    float rn1 = (l1 > 0.f) ? 1.f / l1 : 0.f;
    float rn2 = (l2 > 0.f) ? 1.f / l2 : 0.f;
    int row1 = q0 + wm + (lane >> 2);
    int row2 = row1 + 8;
    #pragma unroll
    for (int nf = 0; nf < 16; nf++) {
        int col = h * HD + nf * 8 + (lane & 3) * 2;
        *(__half2*)&g_xf16[(size_t)row1 * QSZ + col] =
            __floats2half2_rn(o[nf][0] * rn1, o[nf][1] * rn1);
        *(__half2*)&g_xf16[(size_t)row2 * QSZ + col] =
            __floats2half2_rn(o[nf][2] * rn2, o[nf][3] * rn2);
    }
}

// ---------------- launch ----------------
extern "C" void kernel_launch(void* const* d_in, const int* in_sizes, int n_in,
                              void* d_out, int out_size) {
    const float* hidden = (const float*)d_in[0];
    const int*   posw   = (const int*)d_in[1];
    const float* w_qkv  = (const float*)d_in[2];
    const float* b_qkv  = (const float*)d_in[3];
    const float* w_o    = (const float*)d_in[4];
    float* out = (float*)d_out;

    void *p_qkv = nullptr, *p_x = nullptr;
    void *p_wqh = nullptr, *p_wql = nullptr, *p_woh = nullptr, *p_wol = nullptr;
    cudaGetSymbolAddress(&p_qkv, g_qkv);
    cudaGetSymbolAddress(&p_x, g_xf16);
    cudaGetSymbolAddress(&p_wqh, g_wqkvT_h);
    cudaGetSymbolAddress(&p_wql, g_wqkvT_l);
    cudaGetSymbolAddress(&p_woh, g_woT_h);
    cudaGetSymbolAddress(&p_wol, g_woT_l);

    const int gemm_smem = 2 * G_STAGE;   // 61440
    cudaFuncSetAttribute(gemm_mma5, cudaFuncAttributeMaxDynamicSharedMemorySize, gemm_smem);

    prep_kernel<<<1, 256>>>(posw);

    to_fp16<<<(SEQ * HID / 4 + 255) / 256, 256>>>(
        (const float4*)hidden, (__half2*)p_x, SEQ * HID / 4);
    split_transpose_fp16<<<dim3(QKVN / 32, HID / 32), dim3(32, 8)>>>(
        w_qkv, (__half*)p_wqh, (__half*)p_wql, HID, QKVN);
    split_transpose_fp16<<<dim3(HID / 32, QSZ / 32), dim3(32, 8)>>>(
        w_o, (__half*)p_woh, (__half*)p_wol, QSZ, HID);

    gemm_mma5<<<dim3(QKVN / 128, SEQ / 128), 256, gemm_smem>>>(
        (const __half*)p_x,
        (const __half*)p_wqh, (const __half*)p_wql,
        b_qkv, (float*)p_qkv, SEQ, QKVN, HID);

    int total = SEQ * NH * (HD / 2) + SEQ * NKV * (HD / 2) + SEQ * NKV * (HD / 4);
    rope_split_kernel<<<(total + 255) / 256, 256>>>();

    cudaFuncSetAttribute(flash_mma5_kernel,
                         cudaFuncAttributeMaxDynamicSharedMemorySize, FB_TOTAL);
    flash_mma5_kernel<<<dim3(SEQ / 64, NH), 128, FB_TOTAL>>>();

    gemm_mma5<<<dim3(HID / 128, SEQ / 128), 256, gemm_smem>>>(
        (const __half*)p_x,
        (const __half*)p_woh, (const __half*)p_wol,
        nullptr, out, SEQ, HID, QSZ);
}

// round 17
// speedup vs baseline: 1.1818x; 1.0196x over previous
#include <cuda_runtime.h>
#include <cuda_bf16.h>
#include <cuda_fp16.h>
#include <math.h>
#include <cstdint>

#define SEQ   2048
#define NH    16
#define NKV   2
#define HD    128
#define QSZ   (NH * HD)            // 2048
#define KVSZ  (NKV * HD)           // 256
#define QKVN  (QSZ + 2 * KVSZ)     // 2560
#define HID   2048
#define GROUPS (NH / NKV)          // 8

// ---------------- scratch (device globals; no allocs allowed) ----------------
__device__ int   g_pos[SEQ];
__device__ int   g_segstart[SEQ];
__device__ float g_invf[HD / 2];

// fp16 attention operands (2-term path: Q plain, K/V split hi/lo)
__device__ __half g_qf[NH * SEQ * HD];      // [h][s][d]
__device__ __half g_kh[NKV * SEQ * HD];     // [kvh][s][d]
__device__ __half g_kl[NKV * SEQ * HD];
__device__ __half g_vTh[NKV * HD * SEQ];    // [kvh][d][s]  (transposed)
__device__ __half g_vTl[NKV * HD * SEQ];

// fp16 GEMM operands (2-term path: A plain fp16, W split hi/lo fp16)
__device__ __half g_xf16[SEQ * HID];        // activation (hidden, then attn out)
__device__ __half g_wqkvT_h[QKVN * HID];    // w_qkv^T  [2560][2048]
__device__ __half g_wqkvT_l[QKVN * HID];
__device__ __half g_woT_h[HID * QSZ];       // w_o^T    [2048][2048]
__device__ __half g_woT_l[HID * QSZ];

__device__ __forceinline__ uint32_t smem_u32(const void* p) {
    uint32_t a;
    asm("{ .reg .u64 t; cvta.to.shared.u64 t, %1; cvt.u32.u64 %0, t; }" : "=r"(a) : "l"(p));
    return a;
}

#define CP_ASYNC16(smem_addr, gptr) \
    asm volatile("cp.async.cg.shared.global [%0], [%1], 16;\n" \
        :: "r"((uint32_t)(smem_addr)), "l"(gptr))

__device__ __forceinline__ void ldmatrix_x4(uint32_t* r, uint32_t addr) {
    asm volatile("ldmatrix.sync.aligned.m8n8.x4.shared.b16 {%0,%1,%2,%3}, [%4];"
        : "=r"(r[0]), "=r"(r[1]), "=r"(r[2]), "=r"(r[3]) : "r"(addr));
}

__device__ __forceinline__ void mma_fp16(float* c, const uint32_t* a, uint32_t b0, uint32_t b1) {
    asm volatile(
        "mma.sync.aligned.m16n8k16.row.col.f32.f16.f16.f32 "
        "{%0,%1,%2,%3}, {%4,%5,%6,%7}, {%8,%9}, {%0,%1,%2,%3};"
        : "+f"(c[0]), "+f"(c[1]), "+f"(c[2]), "+f"(c[3])
        : "r"(a[0]), "r"(a[1]), "r"(a[2]), "r"(a[3]), "r"(b0), "r"(b1));
}

// pack two fp32 into f16x2 (lo in low half)
__device__ __forceinline__ uint32_t pack_f16(float lo, float hi) {
    uint32_t r;
    asm("cvt.rn.f16x2.f32 %0, %1, %2;" : "=r"(r) : "f"(hi), "f"(lo));
    return r;
}

// ---------------- prep: decode positions (int32/int64), seg scan ----------------
__global__ void prep_kernel(const int* __restrict__ words) {
    __shared__ int chunk_last[256];
    int tid = threadIdx.x;
    int is64 = (words[1] == 0) ? 1 : 0;

    if (tid < HD / 2) {
        g_invf[tid] = (float)(1.0 / pow(1.0e6, (double)(2 * tid) / (double)HD));
    }

    int base = tid * 8;
    int local_pos[8];
    int run = -1;
    #pragma unroll
    for (int e = 0; e < 8; e++) {
        int i = base + e;
        int p = is64 ? words[2 * i] : words[i];
        if (p < 0) p = 0;
        local_pos[e] = p;
        g_pos[i] = p;
        if (p == 0) run = i;
    }
    chunk_last[tid] = run;
    __syncthreads();
    if (tid == 0) {
        int m = -1;
        for (int t = 0; t < 256; t++) {
            int c = chunk_last[t];
            chunk_last[t] = m;
            m = max(m, c);
        }
    }
    __syncthreads();
    int m = chunk_last[tid];
    #pragma unroll
    for (int e = 0; e < 8; e++) {
        int i = base + e;
        if (local_pos[e] == 0) m = i;
        g_segstart[i] = max(m, 0);
    }
}

// ---------------- fp32 -> fp16 (row-major, vectorized) ----------------
__global__ void to_fp16(const float4* __restrict__ X, __half2* __restrict__ H, int n4) {
    int i = blockIdx.x * blockDim.x + threadIdx.x;
    if (i >= n4) return;
    float4 v = X[i];
    H[2 * i]     = __floats2half2_rn(v.x, v.y);
    H[2 * i + 1] = __floats2half2_rn(v.z, v.w);
}

// ---------------- fp32 W[K][N] -> fp16 hi/lo W^T [N][K] ----------------
__global__ void split_transpose_fp16(const float* __restrict__ W,
                                     __half* __restrict__ Th,
                                     __half* __restrict__ Tl, int K, int N) {
    __shared__ float t[32][33];
    int n0 = blockIdx.x * 32, k0 = blockIdx.y * 32;
    int tx = threadIdx.x, ty = threadIdx.y;   // (32, 8)
    #pragma unroll
    for (int i = 0; i < 32; i += 8)
        t[ty + i][tx] = W[(size_t)(k0 + ty + i) * N + n0 + tx];
    __syncthreads();
    #pragma unroll
    for (int i = 0; i < 32; i += 8) {
        float v = t[tx][ty + i];
        __half h = __float2half_rn(v);
        float lo = v - __half2float(h);
        size_t o = (size_t)(n0 + ty + i) * K + k0 + tx;
        Th[o] = h;
        Tl[o] = __float2half_rn(lo);
    }
}

// ====== HMMA GEMM v5 mainloop (shared by both epilogues) ====================
#define G_STRIDE 40
#define G_A      0u
#define G_BH     10240u
#define G_BL     20480u
#define G_STAGE  30720u

// mainloop producing acc[2][8][4]; caller provides epilogue
#define GEMM_MAINLOOP(A, Bh, Bl, K)                                            \
    extern __shared__ char dsm[];                                              \
    uint32_t sb = smem_u32(dsm);                                               \
    int tid = threadIdx.x, wid = tid >> 5, lane = tid & 31;                    \
    int bx = blockIdx.x, by = blockIdx.y;                                      \
    int wm = (wid >> 1) * 32;                                                  \
    int wn = (wid & 1) * 64;                                                   \
    size_t arow0 = (size_t)by * 128;                                           \
    size_t brow0 = (size_t)bx * 128;                                           \
    int a_row = lane & 15;                                                     \
    int a_k8  = lane >> 4;                                                     \
    int b_row = (lane & 7) + ((lane >> 4) << 3);                               \
    int b_k8  = (lane >> 3) & 1;                                               \
    float acc[2][8][4];                                                        \
    _Pragma("unroll")                                                          \
    for (int i = 0; i < 2; i++)                                                \
        _Pragma("unroll")                                                      \
        for (int j = 0; j < 8; j++)                                            \
            _Pragma("unroll")                                                  \
            for (int e = 0; e < 4; e++) acc[i][j][e] = 0.f;                    \
    int nchunks = (K) >> 5;                                                    \
    auto prefetch = [&](int kc, int stg) {                                     \
        int koff = kc << 5;                                                    \
        uint32_t st = sb + (uint32_t)stg * G_STAGE;                            \
        _Pragma("unroll")                                                      \
        for (int u = 0; u < 2; u++) {                                          \
            int c = tid + u * 256;                                             \
            int r = c >> 2, q = c & 3;                                         \
            uint32_t so = (uint32_t)(r * 80 + q * 16);                         \
            CP_ASYNC16(st + G_A  + so, (A)  + (arow0 + r) * (size_t)(K) + koff + q * 8); \
            CP_ASYNC16(st + G_BH + so, (Bh) + (brow0 + r) * (size_t)(K) + koff + q * 8); \
            CP_ASYNC16(st + G_BL + so, (Bl) + (brow0 + r) * (size_t)(K) + koff + q * 8); \
        }                                                                      \
    };                                                                         \
    prefetch(0, 0);                                                            \
    asm volatile("cp.async.commit_group;\n" ::: "memory");                     \
    for (int kc = 0; kc < nchunks; kc++) {                                     \
        int stg = kc & 1;                                                      \
        if (kc + 1 < nchunks) {                                                \
            prefetch(kc + 1, stg ^ 1);                                         \
            asm volatile("cp.async.commit_group;\n" ::: "memory");             \
            asm volatile("cp.async.wait_group 1;\n" ::: "memory");             \
        } else {                                                               \
            asm volatile("cp.async.wait_group 0;\n" ::: "memory");             \
        }                                                                      \
        __syncthreads();                                                       \
        uint32_t stb = sb + (uint32_t)stg * G_STAGE;                           \
        _Pragma("unroll")                                                      \
        for (int ds = 0; ds < 2; ds++) {                                       \
            uint32_t af[2][4];                                                 \
            _Pragma("unroll")                                                  \
            for (int mi = 0; mi < 2; mi++) {                                   \
                uint32_t off = (uint32_t)((wm + mi * 16 + a_row) * G_STRIDE + ds * 16 + a_k8 * 8) * 2; \
                ldmatrix_x4(af[mi], stb + G_A + off);                          \
            }                                                                  \
            _Pragma("unroll")                                                  \
            for (int nb = 0; nb < 4; nb++) {                                   \
                uint32_t boff = (uint32_t)((wn + nb * 16 + b_row) * G_STRIDE + ds * 16 + b_k8 * 8) * 2; \
                uint32_t bhf[4], blf[4];                                       \
                ldmatrix_x4(bhf, stb + G_BH + boff);                           \
                ldmatrix_x4(blf, stb + G_BL + boff);                           \
                _Pragma("unroll")                                              \
                for (int mi = 0; mi < 2; mi++) {                               \
                    mma_fp16(acc[mi][2 * nb],     af[mi], bhf[0], bhf[1]);     \
                    mma_fp16(acc[mi][2 * nb],     af[mi], blf[0], blf[1]);     \
                    mma_fp16(acc[mi][2 * nb + 1], af[mi], bhf[2], bhf[3]);     \
                    mma_fp16(acc[mi][2 * nb + 1], af[mi], blf[2], blf[3]);     \
                }                                                              \
            }                                                                  \
        }                                                                      \
        __syncthreads();                                                       \
    }

// ---- plain GEMM (O projection): C fp32 (+optional bias) --------------------
__global__ __launch_bounds__(256, 2)
void gemm_mma5(const __half* __restrict__ A,
               const __half* __restrict__ Bh, const __half* __restrict__ Bl,
               const float* __restrict__ bias, float* __restrict__ C,
               int M, int N, int K)
{
    GEMM_MAINLOOP(A, Bh, Bl, K)

    int trow = lane >> 2;
    int tcol = (lane & 3) * 2;
    #pragma unroll
    for (int mi = 0; mi < 2; mi++) {
        #pragma unroll
        for (int hh = 0; hh < 2; hh++) {
            size_t row = arow0 + wm + mi * 16 + trow + hh * 8;
            float* crow = C + row * (size_t)N + brow0 + wn;
            #pragma unroll
            for (int nj = 0; nj < 8; nj++) {
                int col = nj * 8 + tcol;
                float2 o;
                o.x = acc[mi][nj][2 * hh];
                o.y = acc[mi][nj][2 * hh + 1];
                if (bias) {
                    o.x += bias[brow0 + wn + col];
                    o.y += bias[brow0 + wn + col + 1];
                }
                *(float2*)(crow + col) = o;
            }
        }
    }
}

// ---- fused QKV GEMM: epilogue applies bias + RoPE and writes fp16 operands --
// Tile column ranges: bx<16 -> Q, bx in {16,17} -> K, bx in {18,19} -> V.
__global__ __launch_bounds__(256, 2)
void gemm_qkv_fused(const __half* __restrict__ A,
                    const __half* __restrict__ Bh, const __half* __restrict__ Bl,
                    const float* __restrict__ bias, int K)
{
    GEMM_MAINLOOP(A, Bh, Bl, K)

    const float qscale = 0.08838834764831845f;   // 1/sqrt(128)
    int trow = lane >> 2;
    int tcol = (lane & 3) * 2;
    int colbase = (int)brow0 + wn;

    #pragma unroll
    for (int mi = 0; mi < 2; mi++) {
        #pragma unroll
        for (int hh = 0; hh < 2; hh++) {
            int row = (int)arow0 + wm + mi * 16 + trow + hh * 8;
            int p = g_pos[row];
            #pragma unroll
            for (int nj = 0; nj < 8; nj++) {
                int col = colbase + nj * 8 + tcol;
                float x1 = acc[mi][nj][2 * hh]     + bias[col];
                float x2 = acc[mi][nj][2 * hh + 1] + bias[col + 1];
                if (col < QSZ) {
                    // Q: rope + scale, plain fp16
                    int hq = col >> 7, d = col & 127, j = d >> 1;
                    float sn, cs;
                    sincosf((float)p * g_invf[j], &sn, &cs);
                    float re = (x1 * cs - x2 * sn) * qscale;
                    float im = (x1 * sn + x2 * cs) * qscale;
                    *(__half2*)&g_qf[((size_t)hq * SEQ + row) * HD + d] =
                        __floats2half2_rn(re, im);
                } else if (col < QSZ + KVSZ) {
                    // K: rope, fp16 hi/lo
                    int cc = col - QSZ;
                    int kvh = cc >> 7, d = cc & 127, j = d >> 1;
                    float sn, cs;
                    sincosf((float)p * g_invf[j], &sn, &cs);
                    float re = x1 * cs - x2 * sn;
                    float im = x1 * sn + x2 * cs;
                    size_t off = ((size_t)kvh * SEQ + row) * HD + d;
                    __half hre = __float2half_rn(re), him = __float2half_rn(im);
                    __half2 hp; hp.x = hre; hp.y = him;
                    *(__half2*)&g_kh[off] = hp;
                    __half2 lp;
                    lp.x = __float2half_rn(re - __half2float(hre));
                    lp.y = __float2half_rn(im - __half2float(him));
                    *(__half2*)&g_kl[off] = lp;
                } else {
                    // V: fp16 hi/lo, transposed [kvh][d][s]
                    int cc = col - QSZ - KVSZ;
                    int kvh = cc >> 7, d = cc & 127;
                    size_t o1 = ((size_t)kvh * HD + d) * SEQ + row;
                    size_t o2 = o1 + SEQ;
                    __half h1 = __float2half_rn(x1);
                    __half h2 = __float2half_rn(x2);
                    g_vTh[o1] = h1;
                    g_vTl[o1] = __float2half_rn(x1 - __half2float(h1));
                    g_vTh[o2] = h2;
                    g_vTl[o2] = __float2half_rn(x2 - __half2float(h2));
                }
            }
        }
    }
}

// ---------------- flash attention v5: fp16 2-term, QT=64, 128 thr, Q in regs, 3 CTAs/SM ----------------
#define FB_KH    0u
#define FB_KL    17408u
#define FB_VH    34816u
#define FB_VL    53248u
#define FB_TOTAL 71680

__global__ __launch_bounds__(128, 3) void flash_mma5_kernel() {
    extern __shared__ char sm8[];
    uint32_t sb = smem_u32(sm8);
    __shared__ int s_ktmin;

    int tid = threadIdx.x, wid = tid >> 5, lane = tid & 31;
    int qt = gridDim.x - 1 - blockIdx.x;   // heavy tiles first
    int h = blockIdx.y, kvh = h >> 3;
    int q0 = qt * 64;
    int wm = wid * 16;                     // 4 warps x m16

    int a_row = lane & 15;
    int a_k8  = lane >> 4;
    int b_row = (lane & 7) + ((lane >> 4) << 3);
    int b_k8  = (lane >> 3) & 1;
    uint32_t q_off = (uint32_t)((wm + a_row) * 136 + a_k8 * 8) * 2;

    const char* khg = (const char*)(g_kh + (size_t)kvh * SEQ * HD);
    const char* klg = (const char*)(g_kl + (size_t)kvh * SEQ * HD);
    const char* vhg = (const char*)(g_vTh + (size_t)kvh * HD * SEQ);
    const char* vlg = (const char*)(g_vTl + (size_t)kvh * HD * SEQ);

    auto load_k = [&](int kt) {
        const char* kh = khg + (size_t)kt * 64 * 256;
        const char* kl = klg + (size_t)kt * 64 * 256;
        #pragma unroll
        for (int u = 0; u < 8; u++) {
            int c = tid + u * 128;
            int r = c >> 4, cc = c & 15;
            CP_ASYNC16(sb + FB_KH + r * 272 + cc * 16, kh + r * 256 + cc * 16);
            CP_ASYNC16(sb + FB_KL + r * 272 + cc * 16, kl + r * 256 + cc * 16);
        }
    };
    auto load_v = [&](int kt) {
        const char* vh = vhg + (size_t)kt * 128;     // 64 el * 2B
        const char* vl = vlg + (size_t)kt * 128;
        #pragma unroll
        for (int u = 0; u < 8; u++) {
            int c = tid + u * 128;
            int vr = c >> 3, vc = c & 7;
            CP_ASYNC16(sb + FB_VH + vr * 144 + vc * 16, vh + (size_t)vr * 4096 + vc * 16);
            CP_ASYNC16(sb + FB_VL + vr * 144 + vc * 16, vl + (size_t)vr * 4096 + vc * 16);
        }
    };

    if (tid == 0) {
        int mn = 0x7fffffff;
        for (int r = 0; r < 64; r++) mn = min(mn, g_segstart[q0 + r]);
        s_ktmin = mn >> 6;
    }

    // ---- stage Q through the KH smem region, cache fragments in registers ----
    {
        const char* qg = (const char*)(g_qf + ((size_t)h * SEQ + q0) * HD);
        #pragma unroll
        for (int u = 0; u < 8; u++) {
            int c = tid + u * 128;
            int r = c >> 4, cc = c & 15;
            CP_ASYNC16(sb + FB_KH + r * 272 + cc * 16, qg + r * 256 + cc * 16);
        }
    }
    asm volatile("cp.async.commit_group;\n" ::: "memory");
    asm volatile("cp.async.wait_group 0;\n" ::: "memory");
    __syncthreads();

    uint32_t qreg[8][4];
    #pragma unroll
    for (int ds = 0; ds < 8; ds++)
        ldmatrix_x4(qreg[ds], sb + FB_KH + q_off + ds * 32);
    __syncthreads();                      // all warps done reading staged Q

    int ktmin = s_ktmin;
    int ktmax = qt;

    load_k(ktmin);
    asm volatile("cp.async.commit_group;\n" ::: "memory");
    load_v(ktmin);
    asm volatile("cp.async.commit_group;\n" ::: "memory");

    int sg1 = q0 + wm + (lane >> 2);
    int sg2 = sg1 + 8;
    int ts1 = g_segstart[sg1], ts2 = g_segstart[sg2];

    float o[16][4];
    #pragma unroll
    for (int i = 0; i < 16; i++)
        #pragma unroll
        for (int e = 0; e < 4; e++) o[i][e] = 0.f;
    float m1 = -1e30f, m2 = -1e30f, l1 = 0.f, l2 = 0.f;

    for (int kt = ktmin; kt <= ktmax; kt++) {
        // entering: pending = {K(kt), V(kt)} -> drain K, V may stay
        asm volatile("cp.async.wait_group 1;\n" ::: "memory");
        __syncthreads();

        // ---- S = Q K^T : fp16 2-term (Q regs, K hi/lo) ----
        float s[8][4];
        #pragma unroll
        for (int f = 0; f < 8; f++)
            #pragma unroll
            for (int e = 0; e < 4; e++) s[f][e] = 0.f;

        #pragma unroll
        for (int ds = 0; ds < 8; ds++) {
            #pragma unroll
            for (int nb = 0; nb < 4; nb++) {
                uint32_t koff = (uint32_t)((nb * 16 + b_row) * 136 + ds * 16 + b_k8 * 8) * 2;
                uint32_t khf[4], klf[4];
                ldmatrix_x4(khf, sb + FB_KH + koff);
                ldmatrix_x4(klf, sb + FB_KL + koff);
                mma_fp16(s[2 * nb],     qreg[ds], khf[0], khf[1]);
                mma_fp16(s[2 * nb],     qreg[ds], klf[0], klf[1]);
                mma_fp16(s[2 * nb + 1], qreg[ds], khf[2], khf[3]);
                mma_fp16(s[2 * nb + 1], qreg[ds], klf[2], klf[3]);
            }
        }
        __syncthreads();                 // all warps done reading K smem
        if (kt < ktmax) {
            load_k(kt + 1);              // overlaps softmax + PV
            asm volatile("cp.async.commit_group;\n" ::: "memory");
        }

        // ---- mask + online softmax ----
        int colb = kt * 64 + (lane & 3) * 2;
        #pragma unroll
        for (int f = 0; f < 8; f++) {
            int t0 = colb + f * 8, t1 = t0 + 1;
            if (t0 > sg1 || t0 < ts1) s[f][0] = -1e30f;
            if (t1 > sg1 || t1 < ts1) s[f][1] = -1e30f;
            if (t0 > sg2 || t0 < ts2) s[f][2] = -1e30f;
            if (t1 > sg2 || t1 < ts2) s[f][3] = -1e30f;
        }

        float mx1 = -1e30f, mx2 = -1e30f;
        #pragma unroll
        for (int f = 0; f < 8; f++) {
            mx1 = fmaxf(mx1, fmaxf(s[f][0], s[f][1]));
            mx2 = fmaxf(mx2, fmaxf(s[f][2], s[f][3]));
        }
        mx1 = fmaxf(mx1, __shfl_xor_sync(0xffffffffu, mx1, 1));
        mx1 = fmaxf(mx1, __shfl_xor_sync(0xffffffffu, mx1, 2));
        mx2 = fmaxf(mx2, __shfl_xor_sync(0xffffffffu, mx2, 1));
        mx2 = fmaxf(mx2, __shfl_xor_sync(0xffffffffu, mx2, 2));
        float mn1 = fmaxf(m1, mx1), mn2 = fmaxf(m2, mx2);
        float a1 = __expf(m1 - mn1), a2 = __expf(m2 - mn2);
        m1 = mn1; m2 = mn2;

        float sum1 = 0.f, sum2 = 0.f;
        #pragma unroll
        for (int f = 0; f < 8; f++) {
            s[f][0] = __expf(s[f][0] - mn1);
            s[f][1] = __expf(s[f][1] - mn1);
            s[f][2] = __expf(s[f][2] - mn2);
            s[f][3] = __expf(s[f][3] - mn2);
            sum1 += s[f][0] + s[f][1];
            sum2 += s[f][2] + s[f][3];
        }
        sum1 += __shfl_xor_sync(0xffffffffu, sum1, 1);
        sum1 += __shfl_xor_sync(0xffffffffu, sum1, 2);
        sum2 += __shfl_xor_sync(0xffffffffu, sum2, 1);
        sum2 += __shfl_xor_sync(0xffffffffu, sum2, 2);
        l1 = l1 * a1 + sum1;
        l2 = l2 * a2 + sum2;

        #pragma unroll
        for (int i = 0; i < 16; i++) {
            o[i][0] *= a1; o[i][1] *= a1;
            o[i][2] *= a2; o[i][3] *= a2;
        }

        // V(kt) must complete. kt<ktmax: pending={V(kt),K(kt+1)} -> wait 1.
        // Last iteration: pending={V(kt)} alone -> wait 0 (round-12 NaN fix).
        if (kt < ktmax) {
            asm volatile("cp.async.wait_group 1;\n" ::: "memory");
        } else {
            asm volatile("cp.async.wait_group 0;\n" ::: "memory");
        }
        __syncthreads();

        // ---- O += P V : fp16 2-term (P plain, V hi/lo) ----
        #pragma unroll
        for (int kk = 0; kk < 4; kk++) {
            uint32_t ph[4];
            ph[0] = pack_f16(s[2 * kk][0],     s[2 * kk][1]);
            ph[1] = pack_f16(s[2 * kk][2],     s[2 * kk][3]);
            ph[2] = pack_f16(s[2 * kk + 1][0], s[2 * kk + 1][1]);
            ph[3] = pack_f16(s[2 * kk + 1][2], s[2 * kk + 1][3]);
            #pragma unroll
            for (int nb = 0; nb < 8; nb++) {
                uint32_t voff = (uint32_t)((nb * 16 + b_row) * 72 + kk * 16 + b_k8 * 8) * 2;
                uint32_t vhf[4], vlf[4];
                ldmatrix_x4(vhf, sb + FB_VH + voff);
                ldmatrix_x4(vlf, sb + FB_VL + voff);
                mma_fp16(o[2 * nb],     ph, vhf[0], vhf[1]);
                mma_fp16(o[2 * nb],     ph, vlf[0], vlf[1]);
                mma_fp16(o[2 * nb + 1], ph, vhf[2], vhf[3]);
                mma_fp16(o[2 * nb + 1], ph, vlf[2], vlf[3]);
            }
        }
        __syncthreads();                 // all warps done reading V smem
        if (kt < ktmax) {
            load_v(kt + 1);
            asm volatile("cp.async.commit_group;\n" ::: "memory");
        }
    }

    // ---- finalize: write attn output directly as fp16 (O-proj A operand) ----
    float rn1 = (l1 > 0.f) ? 1.f / l1 : 0.f;
    float rn2 = (l2 > 0.f) ? 1.f / l2 : 0.f;
    int row1 = q0 + wm + (lane >> 2);
    int row2 = row1 + 8;
    #pragma unroll
    for (int nf = 0; nf < 16; nf++) {
        int col = h * HD + nf * 8 + (lane & 3) * 2;
        *(__half2*)&g_xf16[(size_t)row1 * QSZ + col] =
            __floats2half2_rn(o[nf][0] * rn1, o[nf][1] * rn1);
        *(__half2*)&g_xf16[(size_t)row2 * QSZ + col] =
            __floats2half2_rn(o[nf][2] * rn2, o[nf][3] * rn2);
    }
}

// ---------------- launch ----------------
extern "C" void kernel_launch(void* const* d_in, const int* in_sizes, int n_in,
                              void* d_out, int out_size) {
    const float* hidden = (const float*)d_in[0];
    const int*   posw   = (const int*)d_in[1];
    const float* w_qkv  = (const float*)d_in[2];
    const float* b_qkv  = (const float*)d_in[3];
    const float* w_o    = (const float*)d_in[4];
    float* out = (float*)d_out;

    void *p_x = nullptr;
    void *p_wqh = nullptr, *p_wql = nullptr, *p_woh = nullptr, *p_wol = nullptr;
    cudaGetSymbolAddress(&p_x, g_xf16);
    cudaGetSymbolAddress(&p_wqh, g_wqkvT_h);
    cudaGetSymbolAddress(&p_wql, g_wqkvT_l);
    cudaGetSymbolAddress(&p_woh, g_woT_h);
    cudaGetSymbolAddress(&p_wol, g_woT_l);

    const int gemm_smem = 2 * G_STAGE;   // 61440
    cudaFuncSetAttribute(gemm_mma5, cudaFuncAttributeMaxDynamicSharedMemorySize, gemm_smem);
    cudaFuncSetAttribute(gemm_qkv_fused, cudaFuncAttributeMaxDynamicSharedMemorySize, gemm_smem);

    prep_kernel<<<1, 256>>>(posw);

    to_fp16<<<(SEQ * HID / 4 + 255) / 256, 256>>>(
        (const float4*)hidden, (__half2*)p_x, SEQ * HID / 4);
    split_transpose_fp16<<<dim3(QKVN / 32, HID / 32), dim3(32, 8)>>>(
        w_qkv, (__half*)p_wqh, (__half*)p_wql, HID, QKVN);
    split_transpose_fp16<<<dim3(HID / 32, QSZ / 32), dim3(32, 8)>>>(
        w_o, (__half*)p_woh, (__half*)p_wol, QSZ, HID);

    // fused QKV projection + bias + RoPE + operand split
    gemm_qkv_fused<<<dim3(QKVN / 128, SEQ / 128), 256, gemm_smem>>>(
        (const __half*)p_x,
        (const __half*)p_wqh, (const __half*)p_wql,
        b_qkv, HID);

    cudaFuncSetAttribute(flash_mma5_kernel,
                         cudaFuncAttributeMaxDynamicSharedMemorySize, FB_TOTAL);
    flash_mma5_kernel<<<dim3(SEQ / 64, NH), 128, FB_TOTAL>>>();

    gemm_mma5<<<dim3(HID / 128, SEQ / 128), 256, gemm_smem>>>(
        (const __half*)p_x,
        (const __half*)p_woh, (const __half*)p_wol,
        nullptr, out, SEQ, HID, QSZ);
}